// round 16
// baseline (speedup 1.0000x reference)
#include <cuda_runtime.h>
#include <cuda_bf16.h>

#define BB 4
#define FF 9976
#define FPAD 9984
#define NV 5023
#define HH 224
#define WW 224
#define NPIX (HH*WW)
#define EPSR 1e-8f
#define BIGD 1000000.0f
#define CHT 128               // triangles per smem chunk
#define QNAN __int_as_float(0x7fc00000)
#define INV224 (1.0f / 224.0f)
#define BBOX_EMPTY 0x00FF00FFu   // xmn=255,xmx=0,ymn=255,ymx=0 -> never overlaps

// Per-triangle setup: 3 float4 per triangle
//  T[0] = {dy12, dx21, dy20, dx02}
//  T[1] = {x2,   y2,   inv_den, bbox(u8x4)}  (inv_den = NaN if degenerate/pad)
//  T[2] = {iz0,  iz1,  iz2,  0}
static __device__ float4 g_T[BB * FPAD * 3];

// CONFIRMED transform (R15 pass): plain two-rounding mul/add, /224 as
// standalone recip-mul by rn(1/224), -1 add separate & plain.
__device__ __forceinline__ float xform_xy(float v) {
    float s = __fadd_rn(__fmul_rn(-v, 112.0f), 112.0f);
    s = __fadd_rn(223.0f, -s);
    float t = __fadd_rn(__fmul_rn(2.0f, s), 1.0f);
    t = __fmul_rn(t, INV224);
    s = __fadd_rn(-1.0f, t);
    s = __fadd_rn(__fmul_rn(s, 112.0f), 112.0f);
    return s;
}

__global__ void setup_kernel(const float* __restrict__ verts,
                             const int*   __restrict__ faces) {
    int i = blockIdx.x * blockDim.x + threadIdx.x;
    if (i >= BB * FPAD) return;
    int b = i / FPAD;
    int f = i - b * FPAD;

    float4 A, Bv, C;
    if (f >= FF) {
        A  = make_float4(0.f, 0.f, 0.f, 0.f);
        Bv = make_float4(0.f, 0.f, QNAN, __uint_as_float(BBOX_EMPTY));
        C  = make_float4(0.f, 0.f, 0.f, 0.f);
    } else {
        const int* fp = faces + ((size_t)b * FF + f) * 3;
        float xs[3], ys[3], zs[3];
        #pragma unroll
        for (int k = 0; k < 3; k++) {
            int vi = fp[k];
            const float* vp = verts + ((size_t)b * NV + vi) * 3;
            xs[k] = xform_xy(vp[0]);
            ys[k] = xform_xy(vp[1]);
            zs[k] = __fmul_rn(vp[2], 112.0f);
        }
        float dy12 = ys[1] - ys[2];
        float dx21 = xs[2] - xs[1];
        float dy20 = ys[2] - ys[0];
        float dx02 = xs[0] - xs[2];
        float dy02 = ys[0] - ys[2];
        float denom = __fmaf_rn(dy12, dx02, __fmul_rn(dx21, dy02));
        bool ok = fabsf(denom) > EPSR;
        float inv_den = ok ? __fdiv_rn(1.0f, denom) : QNAN;
        float iz0 = __fdiv_rn(1.0f, (fabsf(zs[0]) > EPSR) ? zs[0] : 1.0f);
        float iz1 = __fdiv_rn(1.0f, (fabsf(zs[1]) > EPSR) ? zs[1] : 1.0f);
        float iz2 = __fdiv_rn(1.0f, (fabsf(zs[2]) > EPSR) ? zs[2] : 1.0f);

        // conservative pixel bbox (fp inside-test slop << 1 px; margin = 1 px)
        float xmn = fminf(fminf(xs[0], xs[1]), xs[2]) - 1.0f;
        float xmx = fmaxf(fmaxf(xs[0], xs[1]), xs[2]) + 1.0f;
        float ymn = fminf(fminf(ys[0], ys[1]), ys[2]) - 1.0f;
        float ymx = fmaxf(fmaxf(ys[0], ys[1]), ys[2]) + 1.0f;
        unsigned int packed;
        if (!ok || xmx < 0.f || xmn > 223.f || ymx < 0.f || ymn > 223.f) {
            packed = BBOX_EMPTY;   // degenerate or fully off-screen
        } else {
            int ix0 = max(0,   (int)floorf(xmn));
            int ix1 = min(223, (int)ceilf(xmx));
            int iy0 = max(0,   (int)floorf(ymn));
            int iy1 = min(223, (int)ceilf(ymx));
            packed = (unsigned)ix0 | ((unsigned)ix1 << 8) |
                     ((unsigned)iy0 << 16) | ((unsigned)iy1 << 24);
        }
        A  = make_float4(dy12, dx21, dy20, dx02);
        Bv = make_float4(xs[2], ys[2], inv_den, __uint_as_float(packed));
        C  = make_float4(iz0, iz1, iz2, 0.f);
    }
    float4* t = g_T + (size_t)i * 3;
    t[0] = A; t[1] = Bv; t[2] = C;
}

__global__ __launch_bounds__(128)
void raster_kernel(const float* __restrict__ attrs,
                   float*       __restrict__ out) {
    const int b  = blockIdx.z;
    const int lx = threadIdx.x & 31;
    const int wy = threadIdx.x >> 5;          // warp = one 32x1 row strip
    const int xbase = blockIdx.x * 32;
    const int px = xbase + lx;
    const int py = blockIdx.y * 4 + wy;
    const float pxf = (float)px;
    const float pyf = (float)py;

    __shared__ float4 sT[CHT * 3];

    float bestd = BIGD;
    int   besti = -1;

    const float4* gT = g_T + (size_t)b * FPAD * 3;

    for (int base = 0; base < FPAD; base += CHT) {
        __syncthreads();
        #pragma unroll
        for (int i = threadIdx.x; i < CHT * 3; i += 128)
            sT[i] = gT[(size_t)base * 3 + i];
        __syncthreads();

        #pragma unroll 4
        for (int j = 0; j < CHT; ++j) {
            float4 P1 = sT[j * 3 + 1];
            // warp-uniform bbox rejection (py, xbase uniform per warp)
            unsigned int bb = __float_as_uint(P1.w);
            int xmn = bb & 255, xmx = (bb >> 8) & 255;
            int ymn = (bb >> 16) & 255, ymx = bb >> 24;
            if (py < ymn || py > ymx || xbase + 31 < xmn || xbase > xmx)
                continue;

            float4 P0 = sT[j * 3 + 0];
            float dxp = pxf - P1.x;
            float dyp = pyf - P1.y;
            float n0 = __fmaf_rn(P0.x, dxp, __fmul_rn(P0.y, dyp));
            float n1 = __fmaf_rn(P0.z, dxp, __fmul_rn(P0.w, dyp));
            float w0 = __fmul_rn(n0, P1.z);
            float w1 = __fmul_rn(n1, P1.z);
            float w2 = __fadd_rn(__fadd_rn(1.0f, -w0), -w1);   // plain
            bool inside = (w0 >= 0.0f) & (w1 >= 0.0f) & (w2 >= 0.0f);
            if (__any_sync(0xffffffffu, inside)) {
                float4 P2 = sT[j * 3 + 2];
                float m1   = __fmul_rn(w1, P2.y);
                float invd = __fmaf_rn(w2, P2.z, __fmaf_rn(w0, P2.x, m1));
                float x = (fabsf(invd) > EPSR) ? invd : 1.0f;
                // approx 1/x prefilter: exact div only when it could win
                float ra;
                asm("rcp.approx.f32 %0, %1;" : "=f"(ra) : "f"(x));
                float thr = __fmaf_rn(fabsf(ra), 4e-6f, bestd);
                if (inside && (ra <= thr)) {
                    float dep = __fdiv_rn(1.0f, x);            // exact, bit-true
                    if (dep < bestd) { bestd = dep; besti = base + j; }
                }
            }
        }
    }

    // ---- epilogue: recompute winner (exact shapes), gather attrs, 17 ch
    const int oidx = py * WW + px;
    float* outb = out + (size_t)b * 17 * NPIX;

    if (besti < 0) {
        #pragma unroll
        for (int d = 0; d < 17; d++)
            outb[(size_t)d * NPIX + oidx] = 0.0f;
        return;
    }

    float4 A  = gT[(size_t)besti * 3 + 0];
    float4 Bv = gT[(size_t)besti * 3 + 1];
    float4 C  = gT[(size_t)besti * 3 + 2];
    float dxp = pxf - Bv.x;
    float dyp = pyf - Bv.y;
    float n0 = __fmaf_rn(A.x, dxp, __fmul_rn(A.y, dyp));
    float n1 = __fmaf_rn(A.z, dxp, __fmul_rn(A.w, dyp));
    float w0 = __fmul_rn(n0, Bv.z);
    float w1 = __fmul_rn(n1, Bv.z);
    float w2 = __fadd_rn(__fadd_rn(1.0f, -w0), -w1);
    float m1 = __fmul_rn(w1, C.y);
    float invd = __fmaf_rn(w2, C.z, __fmaf_rn(w0, C.x, m1));
    float dep  = __fdiv_rn(1.0f, (fabsf(invd) > EPSR) ? invd : 1.0f);
    // bary_k = mul(mul(w_k, iz_k), dep)
    float b0 = __fmul_rn(__fmul_rn(w0, C.x), dep);
    float b1 = __fmul_rn(__fmul_rn(w1, C.y), dep);
    float b2 = __fmul_rn(__fmul_rn(w2, C.z), dep);

    const float4* ap = (const float4*)(attrs + ((size_t)b * FF + besti) * 48);
    #pragma unroll
    for (int q = 0; q < 4; q++) {
        float4 v0 = ap[q + 0];
        float4 v1 = ap[q + 4];
        float4 v2 = ap[q + 8];
        float4 pv;
        pv.x = __fmaf_rn(b2, v2.x, __fmaf_rn(b0, v0.x, __fmul_rn(b1, v1.x)));
        pv.y = __fmaf_rn(b2, v2.y, __fmaf_rn(b0, v0.y, __fmul_rn(b1, v1.y)));
        pv.z = __fmaf_rn(b2, v2.z, __fmaf_rn(b0, v0.z, __fmul_rn(b1, v1.z)));
        pv.w = __fmaf_rn(b2, v2.w, __fmaf_rn(b0, v0.w, __fmul_rn(b1, v1.w)));
        int d = q * 4;
        outb[(size_t)(d + 0) * NPIX + oidx] = pv.x;
        outb[(size_t)(d + 1) * NPIX + oidx] = pv.y;
        outb[(size_t)(d + 2) * NPIX + oidx] = pv.z;
        outb[(size_t)(d + 3) * NPIX + oidx] = pv.w;
    }
    outb[(size_t)16 * NPIX + oidx] = 1.0f;
}

extern "C" void kernel_launch(void* const* d_in, const int* in_sizes, int n_in,
                              void* d_out, int out_size) {
    // Identify inputs by element count — robust to metadata ordering.
    const float* vertices = nullptr;
    const int*   faces    = nullptr;
    const float* attrs    = nullptr;
    for (int i = 0; i < n_in; i++) {
        if      (in_sizes[i] == 60276)   vertices = (const float*)d_in[i];
        else if (in_sizes[i] == 119712)  faces    = (const int*)  d_in[i];
        else if (in_sizes[i] == 1915392) attrs    = (const float*)d_in[i];
    }
    float* out = (float*)d_out;  // [4,17,224,224] f32

    {
        int n = BB * FPAD;
        setup_kernel<<<(n + 255) / 256, 256>>>(vertices, faces);
    }
    {
        dim3 grid(WW / 32, HH / 4, BB);   // 32x4 tiles, 128 threads, 1568 blocks
        raster_kernel<<<grid, 128>>>(attrs, out);
    }
}

// round 17
// speedup vs baseline: 1.4043x; 1.4043x over previous
#include <cuda_runtime.h>
#include <cuda_bf16.h>

#define BB 4
#define FF 9976
#define FPAD 9984
#define NV 5023
#define HH 224
#define WW 224
#define NPIX (HH*WW)
#define EPSR 1e-8f
#define BIGD 1000000.0f
#define CHT 128               // triangles per smem chunk
#define QNAN __int_as_float(0x7fc00000)
#define INV224 (1.0f / 224.0f)

// Per-triangle setup: 3 float4 per triangle
//  T[0] = {dy12, dx21, dy20, dx02}
//  T[1] = {x2,   y2,   inv_den, 0}   (inv_den = NaN if degenerate/padding)
//  T[2] = {iz0,  iz1,  iz2,  0}
static __device__ float4 g_T[BB * FPAD * 3];

// CONFIRMED transform (R15 pass): plain two-rounding mul/add, /224 as
// standalone recip-mul by rn(1/224), -1 add separate & plain.
__device__ __forceinline__ float xform_xy(float v) {
    float s = __fadd_rn(__fmul_rn(-v, 112.0f), 112.0f);
    s = __fadd_rn(223.0f, -s);
    float t = __fadd_rn(__fmul_rn(2.0f, s), 1.0f);
    t = __fmul_rn(t, INV224);
    s = __fadd_rn(-1.0f, t);
    s = __fadd_rn(__fmul_rn(s, 112.0f), 112.0f);
    return s;
}

__global__ void setup_kernel(const float* __restrict__ verts,
                             const int*   __restrict__ faces) {
    int i = blockIdx.x * blockDim.x + threadIdx.x;
    if (i >= BB * FPAD) return;
    int b = i / FPAD;
    int f = i - b * FPAD;

    float4 A, Bv, C;
    if (f >= FF) {
        A  = make_float4(0.f, 0.f, 0.f, 0.f);
        Bv = make_float4(0.f, 0.f, QNAN, 0.f);
        C  = make_float4(0.f, 0.f, 0.f, 0.f);
    } else {
        const int* fp = faces + ((size_t)b * FF + f) * 3;
        float xs[3], ys[3], zs[3];
        #pragma unroll
        for (int k = 0; k < 3; k++) {
            int vi = fp[k];
            const float* vp = verts + ((size_t)b * NV + vi) * 3;
            xs[k] = xform_xy(vp[0]);
            ys[k] = xform_xy(vp[1]);
            zs[k] = __fmul_rn(vp[2], 112.0f);
        }
        float dy12 = ys[1] - ys[2];
        float dx21 = xs[2] - xs[1];
        float dy20 = ys[2] - ys[0];
        float dx02 = xs[0] - xs[2];
        float dy02 = ys[0] - ys[2];
        float denom = __fmaf_rn(dy12, dx02, __fmul_rn(dx21, dy02));
        float inv_den = (fabsf(denom) > EPSR) ? __fdiv_rn(1.0f, denom) : QNAN;
        float iz0 = __fdiv_rn(1.0f, (fabsf(zs[0]) > EPSR) ? zs[0] : 1.0f);
        float iz1 = __fdiv_rn(1.0f, (fabsf(zs[1]) > EPSR) ? zs[1] : 1.0f);
        float iz2 = __fdiv_rn(1.0f, (fabsf(zs[2]) > EPSR) ? zs[2] : 1.0f);
        A  = make_float4(dy12, dx21, dy20, dx02);
        Bv = make_float4(xs[2], ys[2], inv_den, 0.f);
        C  = make_float4(iz0, iz1, iz2, 0.f);
    }
    float4* t = g_T + (size_t)i * 3;
    t[0] = A; t[1] = Bv; t[2] = C;
}

__global__ __launch_bounds__(256)
void raster_kernel(const float* __restrict__ attrs,
                   float*       __restrict__ out) {
    const int b   = blockIdx.z;
    const int lx  = threadIdx.x & 31;
    const int wid = threadIdx.x >> 5;
    const int px  = blockIdx.x * 32 + lx;
    const int py0 = blockIdx.y * 16 + wid * 2;   // thread owns rows py0, py0+1
    const float pxf  = (float)px;
    const float pyf0 = (float)py0;
    const float pyf1 = (float)(py0 + 1);

    __shared__ float4 sT[CHT * 3];

    float bestd0 = BIGD, bestd1 = BIGD;
    int   besti0 = -1,   besti1 = -1;

    const float4* gT = g_T + (size_t)b * FPAD * 3;

    for (int base = 0; base < FPAD; base += CHT) {
        __syncthreads();
        for (int i = threadIdx.x; i < CHT * 3; i += 256)
            sT[i] = gT[(size_t)base * 3 + i];
        __syncthreads();

        #pragma unroll 4
        for (int j = 0; j < CHT; ++j) {
            float4 A  = sT[j * 3 + 0];
            float4 Bv = sT[j * 3 + 1];
            float dxp  = pxf  - Bv.x;           // shared between both rows
            float dyp0 = pyf0 - Bv.y;
            float dyp1 = pyf1 - Bv.y;
            // row 0
            float n00 = __fmaf_rn(A.x, dxp, __fmul_rn(A.y, dyp0));
            float n10 = __fmaf_rn(A.z, dxp, __fmul_rn(A.w, dyp0));
            float w00 = __fmul_rn(n00, Bv.z);
            float w10 = __fmul_rn(n10, Bv.z);
            float w20 = __fadd_rn(__fadd_rn(1.0f, -w00), -w10);
            bool in0 = (w00 >= 0.0f) & (w10 >= 0.0f) & (w20 >= 0.0f);
            // row 1
            float n01 = __fmaf_rn(A.x, dxp, __fmul_rn(A.y, dyp1));
            float n11 = __fmaf_rn(A.z, dxp, __fmul_rn(A.w, dyp1));
            float w01 = __fmul_rn(n01, Bv.z);
            float w11 = __fmul_rn(n11, Bv.z);
            float w21 = __fadd_rn(__fadd_rn(1.0f, -w01), -w11);
            bool in1 = (w01 >= 0.0f) & (w11 >= 0.0f) & (w21 >= 0.0f);

            if (__any_sync(0xffffffffu, in0 | in1)) {
                float4 C = sT[j * 3 + 2];
                // row 0 depth (FUSED invd shape — confirmed)
                float m10   = __fmul_rn(w10, C.y);
                float invd0 = __fmaf_rn(w20, C.z, __fmaf_rn(w00, C.x, m10));
                float x0 = (fabsf(invd0) > EPSR) ? invd0 : 1.0f;
                float ra0;
                asm("rcp.approx.f32 %0, %1;" : "=f"(ra0) : "f"(x0));
                if (in0 && (ra0 <= __fmaf_rn(fabsf(ra0), 4e-6f, bestd0))) {
                    float dep0 = __fdiv_rn(1.0f, x0);          // exact, bit-true
                    if (dep0 < bestd0) { bestd0 = dep0; besti0 = base + j; }
                }
                // row 1 depth
                float m11   = __fmul_rn(w11, C.y);
                float invd1 = __fmaf_rn(w21, C.z, __fmaf_rn(w01, C.x, m11));
                float x1 = (fabsf(invd1) > EPSR) ? invd1 : 1.0f;
                float ra1;
                asm("rcp.approx.f32 %0, %1;" : "=f"(ra1) : "f"(x1));
                if (in1 && (ra1 <= __fmaf_rn(fabsf(ra1), 4e-6f, bestd1))) {
                    float dep1 = __fdiv_rn(1.0f, x1);          // exact, bit-true
                    if (dep1 < bestd1) { bestd1 = dep1; besti1 = base + j; }
                }
            }
        }
    }

    // ---- epilogue: per owned row, recompute winner, gather attrs, 17 ch
    float* outb = out + (size_t)b * 17 * NPIX;

    #pragma unroll
    for (int r = 0; r < 2; r++) {
        const int py    = py0 + r;
        const int besti = r ? besti1 : besti0;
        const float pyf = r ? pyf1 : pyf0;
        const int oidx  = py * WW + px;

        if (besti < 0) {
            #pragma unroll
            for (int d = 0; d < 17; d++)
                outb[(size_t)d * NPIX + oidx] = 0.0f;
            continue;
        }

        float4 A  = gT[(size_t)besti * 3 + 0];
        float4 Bv = gT[(size_t)besti * 3 + 1];
        float4 C  = gT[(size_t)besti * 3 + 2];
        float dxp = pxf - Bv.x;
        float dyp = pyf - Bv.y;
        float n0 = __fmaf_rn(A.x, dxp, __fmul_rn(A.y, dyp));
        float n1 = __fmaf_rn(A.z, dxp, __fmul_rn(A.w, dyp));
        float w0 = __fmul_rn(n0, Bv.z);
        float w1 = __fmul_rn(n1, Bv.z);
        float w2 = __fadd_rn(__fadd_rn(1.0f, -w0), -w1);
        float m1 = __fmul_rn(w1, C.y);
        float invd = __fmaf_rn(w2, C.z, __fmaf_rn(w0, C.x, m1));
        float dep  = __fdiv_rn(1.0f, (fabsf(invd) > EPSR) ? invd : 1.0f);
        float b0 = __fmul_rn(__fmul_rn(w0, C.x), dep);
        float b1 = __fmul_rn(__fmul_rn(w1, C.y), dep);
        float b2 = __fmul_rn(__fmul_rn(w2, C.z), dep);

        const float4* ap = (const float4*)(attrs + ((size_t)b * FF + besti) * 48);
        #pragma unroll
        for (int q = 0; q < 4; q++) {
            float4 v0 = ap[q + 0];
            float4 v1 = ap[q + 4];
            float4 v2 = ap[q + 8];
            float4 pv;
            pv.x = __fmaf_rn(b2, v2.x, __fmaf_rn(b0, v0.x, __fmul_rn(b1, v1.x)));
            pv.y = __fmaf_rn(b2, v2.y, __fmaf_rn(b0, v0.y, __fmul_rn(b1, v1.y)));
            pv.z = __fmaf_rn(b2, v2.z, __fmaf_rn(b0, v0.z, __fmul_rn(b1, v1.z)));
            pv.w = __fmaf_rn(b2, v2.w, __fmaf_rn(b0, v0.w, __fmul_rn(b1, v1.w)));
            int d = q * 4;
            outb[(size_t)(d + 0) * NPIX + oidx] = pv.x;
            outb[(size_t)(d + 1) * NPIX + oidx] = pv.y;
            outb[(size_t)(d + 2) * NPIX + oidx] = pv.z;
            outb[(size_t)(d + 3) * NPIX + oidx] = pv.w;
        }
        outb[(size_t)16 * NPIX + oidx] = 1.0f;
    }
}

extern "C" void kernel_launch(void* const* d_in, const int* in_sizes, int n_in,
                              void* d_out, int out_size) {
    // Identify inputs by element count — robust to metadata ordering.
    const float* vertices = nullptr;
    const int*   faces    = nullptr;
    const float* attrs    = nullptr;
    for (int i = 0; i < n_in; i++) {
        if      (in_sizes[i] == 60276)   vertices = (const float*)d_in[i];
        else if (in_sizes[i] == 119712)  faces    = (const int*)  d_in[i];
        else if (in_sizes[i] == 1915392) attrs    = (const float*)d_in[i];
    }
    float* out = (float*)d_out;  // [4,17,224,224] f32

    {
        int n = BB * FPAD;
        setup_kernel<<<(n + 255) / 256, 256>>>(vertices, faces);
    }
    {
        dim3 grid(WW / 32, HH / 16, BB);   // 32x16 tiles, 256 threads
        raster_kernel<<<grid, 256>>>(attrs, out);
    }
}